// round 2
// baseline (speedup 1.0000x reference)
#include <cuda_runtime.h>
#include <math.h>

// Problem constants
#define BATCH 4
#define SEQ   2048
#define CMODEL 1024
#define NHEAD 16
#define HDIM  64
#define BH    (BATCH*NHEAD)          // 64
#define MROWS (BATCH*SEQ)            // 8192

// Scratch (allocation-free rule: __device__ globals)
__device__ float g_Q[(size_t)BH*SEQ*HDIM];   // [b*H+h][t][d]
__device__ float g_K[(size_t)BH*SEQ*HDIM];
__device__ float g_V[(size_t)BH*SEQ*HDIM];
__device__ float g_A[(size_t)MROWS*CMODEL];  // attention out, [b*T+t][h*64+d]

// log2(10000)/64
#define ROPE_L2 0.20762050593060493f

// ---------------------------------------------------------------------------
// Kernel 1: QKV GEMM (8192 x 3072 x 1024) + bias + RoPE, scatter to Q/K/V
// block: 256 threads, tile 64x64, BK=16, 4x4 per thread
// ---------------------------------------------------------------------------
__global__ __launch_bounds__(256) void qkv_gemm_kernel(
    const float* __restrict__ x, const float* __restrict__ w,
    const float* __restrict__ bias)
{
    const int K = CMODEL;
    __shared__ float As[16][68];
    __shared__ float Bs[16][68];
    const int tid = threadIdx.x;
    const int tx = tid & 15, ty = tid >> 4;
    const int m0 = blockIdx.y * 64;
    const int n0 = blockIdx.x * 64;

    float acc[4][4] = {};

    const int lr = tid >> 2;         // 0..63
    const int lc = (tid & 3) << 2;   // 0,4,8,12
    const float* Aptr = x + (size_t)(m0 + lr) * K + lc;
    const float* Bptr = w + (size_t)(n0 + lr) * K + lc;

    for (int k0 = 0; k0 < K; k0 += 16) {
        float4 av = *(const float4*)(Aptr + k0);
        float4 bv = *(const float4*)(Bptr + k0);
        __syncthreads();
        As[lc+0][lr]=av.x; As[lc+1][lr]=av.y; As[lc+2][lr]=av.z; As[lc+3][lr]=av.w;
        Bs[lc+0][lr]=bv.x; Bs[lc+1][lr]=bv.y; Bs[lc+2][lr]=bv.z; Bs[lc+3][lr]=bv.w;
        __syncthreads();
        #pragma unroll
        for (int kk = 0; kk < 16; kk++) {
            float a0=As[kk][ty*4+0], a1=As[kk][ty*4+1], a2=As[kk][ty*4+2], a3=As[kk][ty*4+3];
            float b0=Bs[kk][tx*4+0], b1=Bs[kk][tx*4+1], b2=Bs[kk][tx*4+2], b3=Bs[kk][tx*4+3];
            acc[0][0]+=a0*b0; acc[0][1]+=a0*b1; acc[0][2]+=a0*b2; acc[0][3]+=a0*b3;
            acc[1][0]+=a1*b0; acc[1][1]+=a1*b1; acc[1][2]+=a1*b2; acc[1][3]+=a1*b3;
            acc[2][0]+=a2*b0; acc[2][1]+=a2*b1; acc[2][2]+=a2*b2; acc[2][3]+=a2*b3;
            acc[3][0]+=a3*b0; acc[3][1]+=a3*b1; acc[3][2]+=a3*b2; acc[3][3]+=a3*b3;
        }
    }

    // Epilogue: bias + RoPE + scatter
    const int ncol = n0 + tx * 4;        // 4-aligned; all 4 cols same head/which
    const int which = ncol >> 10;        // 0=q,1=k,2=v
    const int c = ncol & 1023;
    const int h = c >> 6;
    const int d0 = c & 63;               // even, 4-aligned
    const float bb0 = bias[ncol+0], bb1 = bias[ncol+1], bb2 = bias[ncol+2], bb3 = bias[ncol+3];
    const float if0 = exp2f(-(float)d0       * ROPE_L2);
    const float if1 = exp2f(-(float)(d0 + 2) * ROPE_L2);

    #pragma unroll
    for (int i = 0; i < 4; i++) {
        const int m = m0 + ty * 4 + i;
        const int b = m >> 11;           // /SEQ
        const int t = m & (SEQ - 1);
        float v0 = acc[i][0] + bb0;
        float v1 = acc[i][1] + bb1;
        float v2 = acc[i][2] + bb2;
        float v3 = acc[i][3] + bb3;
        const size_t base = ((size_t)(b * NHEAD + h) * SEQ + t) * HDIM + d0;
        if (which == 2) {
            g_V[base+0]=v0; g_V[base+1]=v1; g_V[base+2]=v2; g_V[base+3]=v3;
        } else {
            float s0, c0, s1, c1;
            sincosf((float)t * if0, &s0, &c0);
            sincosf((float)t * if1, &s1, &c1);
            float* dst = (which == 0) ? g_Q : g_K;
            dst[base+0] = v0 * c0 - v1 * s0;
            dst[base+1] = v0 * s0 + v1 * c0;
            dst[base+2] = v2 * c1 - v3 * s1;
            dst[base+3] = v2 * s1 + v3 * c1;
        }
    }
}

// ---------------------------------------------------------------------------
// Kernel 2: causal flash attention, fp32.
// grid (SEQ/64, BH), block 64 threads: one query row per thread.
// K/V tiles of 32 rows in shared; per-tile online softmax.
// ---------------------------------------------------------------------------
__global__ __launch_bounds__(64) void attn_kernel()
{
    __shared__ float Ks[32][64];
    __shared__ float Vs[32][64];
    const int tid = threadIdx.x;
    const int bh = blockIdx.y;
    const int q0 = blockIdx.x * 64;
    const int t = q0 + tid;
    const size_t bhbase = (size_t)bh * SEQ * HDIM;

    float q[64], o[64];
    {
        const float4* qp = (const float4*)(g_Q + bhbase + (size_t)t * HDIM);
        #pragma unroll
        for (int d4 = 0; d4 < 16; d4++) {
            float4 v = qp[d4];
            q[4*d4+0]=v.x; q[4*d4+1]=v.y; q[4*d4+2]=v.z; q[4*d4+3]=v.w;
        }
    }
    #pragma unroll
    for (int d = 0; d < 64; d++) o[d] = 0.f;

    float mrun = -1e30f, l = 0.f;

    for (int s0 = 0; s0 <= q0 + 63; s0 += 32) {
        __syncthreads();
        #pragma unroll
        for (int i = tid; i < 512; i += 64) {
            int r = i >> 4, cc = (i & 15) << 2;
            *(float4*)&Ks[r][cc] = *(const float4*)(g_K + bhbase + (size_t)(s0 + r) * HDIM + cc);
            *(float4*)&Vs[r][cc] = *(const float4*)(g_V + bhbase + (size_t)(s0 + r) * HDIM + cc);
        }
        __syncthreads();

        float sc[32];
        float tmax = -1e30f;
        #pragma unroll
        for (int s = 0; s < 32; s++) {
            float acc = 0.f;
            #pragma unroll
            for (int d = 0; d < 64; d += 4) {
                float4 kv = *(float4*)&Ks[s][d];
                acc += q[d]*kv.x + q[d+1]*kv.y + q[d+2]*kv.z + q[d+3]*kv.w;
            }
            acc *= 0.125f;   // 1/sqrt(64)
            sc[s] = (s0 + s <= t) ? acc : -1e30f;
            tmax = fmaxf(tmax, sc[s]);
        }
        if (tmax > -1e29f) {
            const float mnew = fmaxf(mrun, tmax);
            const float corr = __expf(mrun - mnew);
            mrun = mnew;
            l *= corr;
            #pragma unroll
            for (int d = 0; d < 64; d++) o[d] *= corr;
            #pragma unroll
            for (int s = 0; s < 32; s++) {
                const float p = __expf(sc[s] - mnew);
                l += p;
                #pragma unroll
                for (int d = 0; d < 64; d += 4) {
                    float4 vv = *(float4*)&Vs[s][d];
                    o[d]   += p * vv.x;
                    o[d+1] += p * vv.y;
                    o[d+2] += p * vv.z;
                    o[d+3] += p * vv.w;
                }
            }
        }
    }

    const float inv = 1.f / l;
    const int b = bh >> 4, h = bh & 15;
    float* dst = g_A + ((size_t)(b * SEQ + t)) * CMODEL + h * HDIM;
    #pragma unroll
    for (int d = 0; d < 64; d++) dst[d] = o[d] * inv;
}

// ---------------------------------------------------------------------------
// Kernel 3: output projection (8192 x 1024 x 1024) + bias -> d_out
// ---------------------------------------------------------------------------
__global__ __launch_bounds__(256) void proj_gemm_kernel(
    const float* __restrict__ w, const float* __restrict__ bias,
    float* __restrict__ out)
{
    const int K = CMODEL;
    __shared__ float As[16][68];
    __shared__ float Bs[16][68];
    const int tid = threadIdx.x;
    const int tx = tid & 15, ty = tid >> 4;
    const int m0 = blockIdx.y * 64;
    const int n0 = blockIdx.x * 64;

    float acc[4][4] = {};

    const int lr = tid >> 2;
    const int lc = (tid & 3) << 2;
    const float* Aptr = g_A + (size_t)(m0 + lr) * K + lc;
    const float* Bptr = w + (size_t)(n0 + lr) * K + lc;

    for (int k0 = 0; k0 < K; k0 += 16) {
        float4 av = *(const float4*)(Aptr + k0);
        float4 bv = *(const float4*)(Bptr + k0);
        __syncthreads();
        As[lc+0][lr]=av.x; As[lc+1][lr]=av.y; As[lc+2][lr]=av.z; As[lc+3][lr]=av.w;
        Bs[lc+0][lr]=bv.x; Bs[lc+1][lr]=bv.y; Bs[lc+2][lr]=bv.z; Bs[lc+3][lr]=bv.w;
        __syncthreads();
        #pragma unroll
        for (int kk = 0; kk < 16; kk++) {
            float a0=As[kk][ty*4+0], a1=As[kk][ty*4+1], a2=As[kk][ty*4+2], a3=As[kk][ty*4+3];
            float b0=Bs[kk][tx*4+0], b1=Bs[kk][tx*4+1], b2=Bs[kk][tx*4+2], b3=Bs[kk][tx*4+3];
            acc[0][0]+=a0*b0; acc[0][1]+=a0*b1; acc[0][2]+=a0*b2; acc[0][3]+=a0*b3;
            acc[1][0]+=a1*b0; acc[1][1]+=a1*b1; acc[1][2]+=a1*b2; acc[1][3]+=a1*b3;
            acc[2][0]+=a2*b0; acc[2][1]+=a2*b1; acc[2][2]+=a2*b2; acc[2][3]+=a2*b3;
            acc[3][0]+=a3*b0; acc[3][1]+=a3*b1; acc[3][2]+=a3*b2; acc[3][3]+=a3*b3;
        }
    }

    const int ncol = n0 + tx * 4;
    const float bb0 = bias[ncol+0], bb1 = bias[ncol+1], bb2 = bias[ncol+2], bb3 = bias[ncol+3];
    #pragma unroll
    for (int i = 0; i < 4; i++) {
        const int m = m0 + ty * 4 + i;
        float* dst = out + (size_t)m * CMODEL + ncol;
        dst[0] = acc[i][0] + bb0;
        dst[1] = acc[i][1] + bb1;
        dst[2] = acc[i][2] + bb2;
        dst[3] = acc[i][3] + bb3;
    }
}

// ---------------------------------------------------------------------------
extern "C" void kernel_launch(void* const* d_in, const int* in_sizes, int n_in,
                              void* d_out, int out_size)
{
    const float* x      = (const float*)d_in[0];
    const float* qkv_w  = (const float*)d_in[1];
    const float* qkv_b  = (const float*)d_in[2];
    const float* out_w  = (const float*)d_in[3];
    const float* out_b  = (const float*)d_in[4];
    float* out = (float*)d_out;

    qkv_gemm_kernel<<<dim3(3*CMODEL/64, MROWS/64), 256>>>(x, qkv_w, qkv_b);
    attn_kernel<<<dim3(SEQ/64, BH), 64>>>();
    proj_gemm_kernel<<<dim3(CMODEL/64, MROWS/64), 256>>>(out_w, out_b, out);
}

// round 4
// speedup vs baseline: 1.4852x; 1.4852x over previous
#include <cuda_runtime.h>
#include <math.h>
#include <stdint.h>

// Problem constants
#define BATCH 4
#define SEQ   2048
#define CMODEL 1024
#define NHEAD 16
#define HDIM  64
#define BH    (BATCH*NHEAD)          // 64
#define MROWS (BATCH*SEQ)            // 8192

// Scratch (allocation-free rule: __device__ globals)
__device__ float g_Q[(size_t)BH*SEQ*HDIM];   // [b*H+h][t][d]
__device__ float g_K[(size_t)BH*SEQ*HDIM];
__device__ float g_V[(size_t)BH*SEQ*HDIM];
__device__ float g_A[(size_t)MROWS*CMODEL];  // attention out, [b*T+t][h*64+d]

// log2(10000)/64
#define ROPE_L2 0.20762050593060493f

#define KPAD 20   // k-stride in shared (16 used + 4 pad) -> conflict-free frag loads

__device__ __forceinline__ uint32_t f2tf32(float f) {
    uint32_t r;
    asm("cvt.rna.tf32.f32 %0, %1;" : "=r"(r) : "f"(f));
    return r;
}

__device__ __forceinline__ void store_cvt(float* p, float4 v) {
    float4 o;
    o.x = __uint_as_float(f2tf32(v.x));
    o.y = __uint_as_float(f2tf32(v.y));
    o.z = __uint_as_float(f2tf32(v.z));
    o.w = __uint_as_float(f2tf32(v.w));
    *(float4*)p = o;
}

__device__ __forceinline__ void mma_tf32(float4& d, const uint32_t* a, const uint32_t* b) {
    asm volatile(
        "mma.sync.aligned.m16n8k8.row.col.f32.tf32.tf32.f32 "
        "{%0,%1,%2,%3}, {%4,%5,%6,%7}, {%8,%9}, {%0,%1,%2,%3};\n"
        : "+f"(d.x), "+f"(d.y), "+f"(d.z), "+f"(d.w)
        : "r"(a[0]), "r"(a[1]), "r"(a[2]), "r"(a[3]), "r"(b[0]), "r"(b[1]));
}

// Shared mainloop: C[128x128] tile of A(row-major [M][1024]) * B(row-major [N][1024])^T
// 256 threads, 8 warps in 2(M) x 4(N); warp tile 64x32; mma m16n8k8 tf32.
#define GEMM_MAINLOOP(APTR, BPTR)                                                   \
    __shared__ float As[2][128][KPAD];                                              \
    __shared__ float Bs[2][128][KPAD];                                              \
    const int tid = threadIdx.x;                                                    \
    const int w = tid >> 5, lane = tid & 31, g = lane >> 2, tg = lane & 3;          \
    const int wm = (w & 1) * 64, wn = (w >> 1) * 32;                                \
    const int m0 = blockIdx.y * 128, n0 = blockIdx.x * 128;                         \
    const int lr = tid >> 1, lc = (tid & 1) * 8;                                    \
    const float* ga = (APTR) + (size_t)(m0 + lr) * CMODEL + lc;                     \
    const float* gb = (BPTR) + (size_t)(n0 + lr) * CMODEL + lc;                     \
    float4 acc[4][4];                                                               \
    _Pragma("unroll")                                                               \
    for (int i = 0; i < 4; i++)                                                     \
        _Pragma("unroll")                                                           \
        for (int j = 0; j < 4; j++) acc[i][j] = make_float4(0.f, 0.f, 0.f, 0.f);    \
    float4 ra0 = *(const float4*)ga,       ra1 = *(const float4*)(ga + 4);          \
    float4 rb0 = *(const float4*)gb,       rb1 = *(const float4*)(gb + 4);          \
    store_cvt(&As[0][lr][lc], ra0); store_cvt(&As[0][lr][lc + 4], ra1);             \
    store_cvt(&Bs[0][lr][lc], rb0); store_cvt(&Bs[0][lr][lc + 4], rb1);             \
    __syncthreads();                                                                \
    int buf = 0;                                                                    \
    for (int kt = 0; kt < CMODEL / 16; kt++) {                                      \
        if (kt + 1 < CMODEL / 16) {                                                 \
            const float* pa = ga + (kt + 1) * 16;                                   \
            const float* pb = gb + (kt + 1) * 16;                                   \
            ra0 = *(const float4*)pa; ra1 = *(const float4*)(pa + 4);               \
            rb0 = *(const float4*)pb; rb1 = *(const float4*)(pb + 4);               \
        }                                                                           \
        _Pragma("unroll")                                                           \
        for (int ks = 0; ks < 2; ks++) {                                            \
            const int kk = ks * 8;                                                  \
            uint32_t af[4][4], bf[4][2];                                            \
            _Pragma("unroll")                                                       \
            for (int mi = 0; mi < 4; mi++) {                                        \
                const int rbase = wm + mi * 16;                                     \
                af[mi][0] = __float_as_uint(As[buf][rbase + g][kk + tg]);           \
                af[mi][1] = __float_as_uint(As[buf][rbase + g + 8][kk + tg]);       \
                af[mi][2] = __float_as_uint(As[buf][rbase + g][kk + tg + 4]);       \
                af[mi][3] = __float_as_uint(As[buf][rbase + g + 8][kk + tg + 4]);   \
            }                                                                       \
            _Pragma("unroll")                                                       \
            for (int ni = 0; ni < 4; ni++) {                                        \
                const int cbase = wn + ni * 8;                                      \
                bf[ni][0] = __float_as_uint(Bs[buf][cbase + g][kk + tg]);           \
                bf[ni][1] = __float_as_uint(Bs[buf][cbase + g][kk + tg + 4]);       \
            }                                                                       \
            _Pragma("unroll")                                                       \
            for (int mi = 0; mi < 4; mi++)                                          \
                _Pragma("unroll")                                                   \
                for (int ni = 0; ni < 4; ni++)                                      \
                    mma_tf32(acc[mi][ni], af[mi], bf[ni]);                          \
        }                                                                           \
        if (kt + 1 < CMODEL / 16) {                                                 \
            store_cvt(&As[buf ^ 1][lr][lc], ra0);                                   \
            store_cvt(&As[buf ^ 1][lr][lc + 4], ra1);                               \
            store_cvt(&Bs[buf ^ 1][lr][lc], rb0);                                   \
            store_cvt(&Bs[buf ^ 1][lr][lc + 4], rb1);                               \
            __syncthreads();                                                        \
            buf ^= 1;                                                               \
        }                                                                           \
    }

// ---------------------------------------------------------------------------
// Kernel 1: QKV GEMM (8192 x 3072 x 1024) + bias + RoPE -> g_Q, g_K, g_V
// ---------------------------------------------------------------------------
__global__ __launch_bounds__(256) void qkv_gemm_kernel(
    const float* __restrict__ x, const float* __restrict__ wq,
    const float* __restrict__ bias)
{
    GEMM_MAINLOOP(x, wq)

    #pragma unroll
    for (int mi = 0; mi < 4; mi++) {
        #pragma unroll
        for (int ni = 0; ni < 4; ni++) {
            float4 c = acc[mi][ni];
            const int col = n0 + wn + ni * 8 + 2 * tg;   // even
            const int which = col >> 10;                 // 0=q,1=k,2=v
            const int cc = col & 1023;
            const int h = cc >> 6;
            const int d0 = cc & 63;
            const float b0 = bias[col], b1 = bias[col + 1];
            const float invf = exp2f(-(float)d0 * ROPE_L2);
            const int r0 = m0 + wm + mi * 16 + g;
            #pragma unroll
            for (int half = 0; half < 2; half++) {
                const int r = r0 + half * 8;
                const float v0 = (half ? c.z : c.x) + b0;
                const float v1 = (half ? c.w : c.y) + b1;
                const int b = r >> 11;
                const int t = r & (SEQ - 1);
                const size_t base = ((size_t)(b * NHEAD + h) * SEQ + t) * HDIM + d0;
                if (which == 2) {
                    g_V[base] = v0; g_V[base + 1] = v1;
                } else {
                    float s, co;
                    sincosf((float)t * invf, &s, &co);
                    float* dst = which ? g_K : g_Q;
                    dst[base]     = v0 * co - v1 * s;
                    dst[base + 1] = v0 * s  + v1 * co;
                }
            }
        }
    }
}

// ---------------------------------------------------------------------------
// Kernel 2: causal flash attention, fp32 SIMT (unchanged from R2).
// ---------------------------------------------------------------------------
__global__ __launch_bounds__(64) void attn_kernel()
{
    __shared__ float Ks[32][64];
    __shared__ float Vs[32][64];
    const int tid = threadIdx.x;
    const int bh = blockIdx.y;
    const int q0 = blockIdx.x * 64;
    const int t = q0 + tid;
    const size_t bhbase = (size_t)bh * SEQ * HDIM;

    float q[64], o[64];
    {
        const float4* qp = (const float4*)(g_Q + bhbase + (size_t)t * HDIM);
        #pragma unroll
        for (int d4 = 0; d4 < 16; d4++) {
            float4 v = qp[d4];
            q[4*d4+0]=v.x; q[4*d4+1]=v.y; q[4*d4+2]=v.z; q[4*d4+3]=v.w;
        }
    }
    #pragma unroll
    for (int d = 0; d < 64; d++) o[d] = 0.f;

    float mrun = -1e30f, l = 0.f;

    for (int s0 = 0; s0 <= q0 + 63; s0 += 32) {
        __syncthreads();
        #pragma unroll
        for (int i = tid; i < 512; i += 64) {
            int r = i >> 4, cc = (i & 15) << 2;
            *(float4*)&Ks[r][cc] = *(const float4*)(g_K + bhbase + (size_t)(s0 + r) * HDIM + cc);
            *(float4*)&Vs[r][cc] = *(const float4*)(g_V + bhbase + (size_t)(s0 + r) * HDIM + cc);
        }
        __syncthreads();

        float sc[32];
        float tmax = -1e30f;
        #pragma unroll
        for (int s = 0; s < 32; s++) {
            float acc2 = 0.f;
            #pragma unroll
            for (int d = 0; d < 64; d += 4) {
                float4 kv = *(float4*)&Ks[s][d];
                acc2 += q[d]*kv.x + q[d+1]*kv.y + q[d+2]*kv.z + q[d+3]*kv.w;
            }
            acc2 *= 0.125f;   // 1/sqrt(64)
            sc[s] = (s0 + s <= t) ? acc2 : -1e30f;
            tmax = fmaxf(tmax, sc[s]);
        }
        if (tmax > -1e29f) {
            const float mnew = fmaxf(mrun, tmax);
            const float corr = __expf(mrun - mnew);
            mrun = mnew;
            l *= corr;
            #pragma unroll
            for (int d = 0; d < 64; d++) o[d] *= corr;
            #pragma unroll
            for (int s = 0; s < 32; s++) {
                const float p = __expf(sc[s] - mnew);
                l += p;
                #pragma unroll
                for (int d = 0; d < 64; d += 4) {
                    float4 vv = *(float4*)&Vs[s][d];
                    o[d]   += p * vv.x;
                    o[d+1] += p * vv.y;
                    o[d+2] += p * vv.z;
                    o[d+3] += p * vv.w;
                }
            }
        }
    }

    const float inv = 1.f / l;
    const int b = bh >> 4, h = bh & 15;
    float* dst = g_A + ((size_t)(b * SEQ + t)) * CMODEL + h * HDIM;
    #pragma unroll
    for (int d = 0; d < 64; d++) dst[d] = o[d] * inv;
}

// ---------------------------------------------------------------------------
// Kernel 3: output projection (8192 x 1024 x 1024) + bias -> d_out
// ---------------------------------------------------------------------------
__global__ __launch_bounds__(256) void proj_gemm_kernel(
    const float* __restrict__ wo, const float* __restrict__ bias,
    float* __restrict__ out)
{
    GEMM_MAINLOOP(g_A, wo)

    #pragma unroll
    for (int mi = 0; mi < 4; mi++) {
        #pragma unroll
        for (int ni = 0; ni < 4; ni++) {
            float4 c = acc[mi][ni];
            const int col = n0 + wn + ni * 8 + 2 * tg;
            const float b0 = bias[col], b1 = bias[col + 1];
            const int r0 = m0 + wm + mi * 16 + g;
            out[(size_t)r0 * CMODEL + col]           = c.x + b0;
            out[(size_t)r0 * CMODEL + col + 1]       = c.y + b1;
            out[(size_t)(r0 + 8) * CMODEL + col]     = c.z + b0;
            out[(size_t)(r0 + 8) * CMODEL + col + 1] = c.w + b1;
        }
    }
}

// ---------------------------------------------------------------------------
extern "C" void kernel_launch(void* const* d_in, const int* in_sizes, int n_in,
                              void* d_out, int out_size)
{
    const float* x      = (const float*)d_in[0];
    const float* qkv_w  = (const float*)d_in[1];
    const float* qkv_b  = (const float*)d_in[2];
    const float* out_w  = (const float*)d_in[3];
    const float* out_b  = (const float*)d_in[4];
    float* out = (float*)d_out;

    qkv_gemm_kernel<<<dim3(3*CMODEL/128, MROWS/128), 256>>>(x, qkv_w, qkv_b);
    attn_kernel<<<dim3(SEQ/64, BH), 64>>>();
    proj_gemm_kernel<<<dim3(CMODEL/128, MROWS/128), 256>>>(out_w, out_b, out);
}

// round 5
// speedup vs baseline: 2.4076x; 1.6211x over previous
#include <cuda_runtime.h>
#include <math.h>
#include <stdint.h>

// Problem constants
#define BATCH 4
#define SEQ   2048
#define CMODEL 1024
#define NHEAD 16
#define HDIM  64
#define BH    (BATCH*NHEAD)          // 64
#define MROWS (BATCH*SEQ)            // 8192

// Scratch (allocation-free rule: __device__ globals)
__device__ float g_Q[(size_t)BH*SEQ*HDIM];   // [b*H+h][t][d]  (pre-scaled by 1/8, tf32)
__device__ float g_K[(size_t)BH*SEQ*HDIM];
__device__ float g_V[(size_t)BH*SEQ*HDIM];
__device__ float g_A[(size_t)MROWS*CMODEL];  // attention out, [b*T+t][h*64+d]

// log2(10000)/64
#define ROPE_L2 0.20762050593060493f

#define KPAD 20   // GEMM k-stride in shared

__device__ __forceinline__ uint32_t f2tf32(float f) {
    uint32_t r;
    asm("cvt.rna.tf32.f32 %0, %1;" : "=r"(r) : "f"(f));
    return r;
}

__device__ __forceinline__ void store_cvt(float* p, float4 v) {
    float4 o;
    o.x = __uint_as_float(f2tf32(v.x));
    o.y = __uint_as_float(f2tf32(v.y));
    o.z = __uint_as_float(f2tf32(v.z));
    o.w = __uint_as_float(f2tf32(v.w));
    *(float4*)p = o;
}

__device__ __forceinline__ void mma_tf32(float4& d, const uint32_t* a, const uint32_t* b) {
    asm volatile(
        "mma.sync.aligned.m16n8k8.row.col.f32.tf32.tf32.f32 "
        "{%0,%1,%2,%3}, {%4,%5,%6,%7}, {%8,%9}, {%0,%1,%2,%3};\n"
        : "+f"(d.x), "+f"(d.y), "+f"(d.z), "+f"(d.w)
        : "r"(a[0]), "r"(a[1]), "r"(a[2]), "r"(a[3]), "r"(b[0]), "r"(b[1]));
}

// Shared mainloop: C[128x128] tile of A(row-major [M][1024]) * B(row-major [N][1024])^T
#define GEMM_MAINLOOP(APTR, BPTR)                                                   \
    __shared__ float As[2][128][KPAD];                                              \
    __shared__ float Bs[2][128][KPAD];                                              \
    const int tid = threadIdx.x;                                                    \
    const int w = tid >> 5, lane = tid & 31, g = lane >> 2, tg = lane & 3;          \
    const int wm = (w & 1) * 64, wn = (w >> 1) * 32;                                \
    const int m0 = blockIdx.y * 128, n0 = blockIdx.x * 128;                         \
    const int lr = tid >> 1, lc = (tid & 1) * 8;                                    \
    const float* ga = (APTR) + (size_t)(m0 + lr) * CMODEL + lc;                     \
    const float* gb = (BPTR) + (size_t)(n0 + lr) * CMODEL + lc;                     \
    float4 acc[4][4];                                                               \
    _Pragma("unroll")                                                               \
    for (int i = 0; i < 4; i++)                                                     \
        _Pragma("unroll")                                                           \
        for (int j = 0; j < 4; j++) acc[i][j] = make_float4(0.f, 0.f, 0.f, 0.f);    \
    float4 ra0 = *(const float4*)ga,       ra1 = *(const float4*)(ga + 4);          \
    float4 rb0 = *(const float4*)gb,       rb1 = *(const float4*)(gb + 4);          \
    store_cvt(&As[0][lr][lc], ra0); store_cvt(&As[0][lr][lc + 4], ra1);             \
    store_cvt(&Bs[0][lr][lc], rb0); store_cvt(&Bs[0][lr][lc + 4], rb1);             \
    __syncthreads();                                                                \
    int buf = 0;                                                                    \
    for (int kt = 0; kt < CMODEL / 16; kt++) {                                      \
        if (kt + 1 < CMODEL / 16) {                                                 \
            const float* pa = ga + (kt + 1) * 16;                                   \
            const float* pb = gb + (kt + 1) * 16;                                   \
            ra0 = *(const float4*)pa; ra1 = *(const float4*)(pa + 4);               \
            rb0 = *(const float4*)pb; rb1 = *(const float4*)(pb + 4);               \
        }                                                                           \
        _Pragma("unroll")                                                           \
        for (int ks = 0; ks < 2; ks++) {                                            \
            const int kk = ks * 8;                                                  \
            uint32_t af[4][4], bf[4][2];                                            \
            _Pragma("unroll")                                                       \
            for (int mi = 0; mi < 4; mi++) {                                        \
                const int rbase = wm + mi * 16;                                     \
                af[mi][0] = __float_as_uint(As[buf][rbase + g][kk + tg]);           \
                af[mi][1] = __float_as_uint(As[buf][rbase + g + 8][kk + tg]);       \
                af[mi][2] = __float_as_uint(As[buf][rbase + g][kk + tg + 4]);       \
                af[mi][3] = __float_as_uint(As[buf][rbase + g + 8][kk + tg + 4]);   \
            }                                                                       \
            _Pragma("unroll")                                                       \
            for (int ni = 0; ni < 4; ni++) {                                        \
                const int cbase = wn + ni * 8;                                      \
                bf[ni][0] = __float_as_uint(Bs[buf][cbase + g][kk + tg]);           \
                bf[ni][1] = __float_as_uint(Bs[buf][cbase + g][kk + tg + 4]);       \
            }                                                                       \
            _Pragma("unroll")                                                       \
            for (int mi = 0; mi < 4; mi++)                                          \
                _Pragma("unroll")                                                   \
                for (int ni = 0; ni < 4; ni++)                                      \
                    mma_tf32(acc[mi][ni], af[mi], bf[ni]);                          \
        }                                                                           \
        if (kt + 1 < CMODEL / 16) {                                                 \
            store_cvt(&As[buf ^ 1][lr][lc], ra0);                                   \
            store_cvt(&As[buf ^ 1][lr][lc + 4], ra1);                               \
            store_cvt(&Bs[buf ^ 1][lr][lc], rb0);                                   \
            store_cvt(&Bs[buf ^ 1][lr][lc + 4], rb1);                               \
            __syncthreads();                                                        \
            buf ^= 1;                                                               \
        }                                                                           \
    }

// ---------------------------------------------------------------------------
// Kernel 1: QKV GEMM + bias + RoPE -> g_Q (pre-scaled by 0.125), g_K, g_V
// ---------------------------------------------------------------------------
__global__ __launch_bounds__(256) void qkv_gemm_kernel(
    const float* __restrict__ x, const float* __restrict__ wq,
    const float* __restrict__ bias)
{
    GEMM_MAINLOOP(x, wq)

    #pragma unroll
    for (int mi = 0; mi < 4; mi++) {
        #pragma unroll
        for (int ni = 0; ni < 4; ni++) {
            float4 c = acc[mi][ni];
            const int col = n0 + wn + ni * 8 + 2 * tg;   // even
            const int which = col >> 10;                 // 0=q,1=k,2=v
            const int cc = col & 1023;
            const int h = cc >> 6;
            const int d0 = cc & 63;
            const float b0 = bias[col], b1 = bias[col + 1];
            const float invf = exp2f(-(float)d0 * ROPE_L2);
            const int r0 = m0 + wm + mi * 16 + g;
            #pragma unroll
            for (int half = 0; half < 2; half++) {
                const int r = r0 + half * 8;
                float v0 = (half ? c.z : c.x) + b0;
                float v1 = (half ? c.w : c.y) + b1;
                const int b = r >> 11;
                const int t = r & (SEQ - 1);
                const size_t base = ((size_t)(b * NHEAD + h) * SEQ + t) * HDIM + d0;
                if (which == 2) {
                    g_V[base] = v0; g_V[base + 1] = v1;
                } else {
                    float s, co;
                    sincosf((float)t * invf, &s, &co);
                    float r0v = v0 * co - v1 * s;
                    float r1v = v0 * s  + v1 * co;
                    if (which == 0) {  // pre-scale Q by 1/sqrt(64)
                        g_Q[base]     = r0v * 0.125f;
                        g_Q[base + 1] = r1v * 0.125f;
                    } else {
                        g_K[base]     = r0v;
                        g_K[base + 1] = r1v;
                    }
                }
            }
        }
    }
}

// ---------------------------------------------------------------------------
// Kernel 2: causal flash attention with tf32 mma.
// 128 threads (4 warps); Br=64 (16 rows/warp), Bc=64.
// Shared: Ks/Ps aliased [64][68], Vs [64][72].
// ---------------------------------------------------------------------------
#define SPAD 68
#define VPAD 72

__global__ __launch_bounds__(128, 3) void attn_kernel()
{
    __shared__ float Ks[64][SPAD];   // K tile; reused as P tile
    __shared__ float Vs[64][VPAD];   // V tile (row s, col d)

    const int tid = threadIdx.x;
    const int w = tid >> 5, lane = tid & 31, g = lane >> 2, tg = lane & 3;
    const int wq0 = w * 16;                  // warp's query-row base within block
    const int bh = blockIdx.y;
    const int q0 = ((int)gridDim.x - 1 - (int)blockIdx.x) * 64;  // heavy blocks first
    const size_t bhbase = (size_t)bh * SEQ * HDIM;

    const int lr = tid >> 1;                 // staging row 0..63
    const int lc = (tid & 1) * 32;           // staging col base

    // ---- Stage Q (scaled, tf32) into Ks, extract frags to registers ----
    {
        const float* gq = g_Q + bhbase + (size_t)(q0 + lr) * HDIM + lc;
        #pragma unroll
        for (int i = 0; i < 8; i++)
            store_cvt(&Ks[lr][lc + i * 4], *(const float4*)(gq + i * 4));
    }
    __syncthreads();
    uint32_t qf[8][4];
    #pragma unroll
    for (int ks = 0; ks < 8; ks++) {
        const int kk = ks * 8;
        qf[ks][0] = __float_as_uint(Ks[wq0 + g][kk + tg]);
        qf[ks][1] = __float_as_uint(Ks[wq0 + g + 8][kk + tg]);
        qf[ks][2] = __float_as_uint(Ks[wq0 + g][kk + tg + 4]);
        qf[ks][3] = __float_as_uint(Ks[wq0 + g + 8][kk + tg + 4]);
    }

    float4 o[8];
    #pragma unroll
    for (int ni = 0; ni < 8; ni++) o[ni] = make_float4(0.f, 0.f, 0.f, 0.f);
    float m0r = -1e30f, m1r = -1e30f, l0 = 0.f, l1 = 0.f;

    const int lr0 = wq0 + g, lr1 = wq0 + g + 8;   // warp-local query rows

    for (int s0 = 0; s0 <= q0; s0 += 64) {
        __syncthreads();   // previous tile's P/V reads done; Q frags extracted
        // ---- Stage K tile (tf32) and V tile (tf32) ----
        {
            const float* gk = g_K + bhbase + (size_t)(s0 + lr) * HDIM + lc;
            const float* gv = g_V + bhbase + (size_t)(s0 + lr) * HDIM + lc;
            #pragma unroll
            for (int i = 0; i < 8; i++) {
                store_cvt(&Ks[lr][lc + i * 4], *(const float4*)(gk + i * 4));
                store_cvt(&Vs[lr][lc + i * 4], *(const float4*)(gv + i * 4));
            }
        }
        __syncthreads();

        // ---- S = Q * K^T (warp rows x 64 keys) ----
        float4 s[8];
        #pragma unroll
        for (int ni = 0; ni < 8; ni++) s[ni] = make_float4(0.f, 0.f, 0.f, 0.f);
        #pragma unroll
        for (int ks = 0; ks < 8; ks++) {
            const int kk = ks * 8;
            #pragma unroll
            for (int ni = 0; ni < 8; ni++) {
                uint32_t bfr[2];
                bfr[0] = __float_as_uint(Ks[ni * 8 + g][kk + tg]);
                bfr[1] = __float_as_uint(Ks[ni * 8 + g][kk + tg + 4]);
                mma_tf32(s[ni], qf[ks], bfr);
            }
        }

        // ---- causal mask (diagonal tile only) ----
        if (s0 == q0) {
            #pragma unroll
            for (int ni = 0; ni < 8; ni++) {
                const int c0 = ni * 8 + 2 * tg, c1 = c0 + 1;
                if (c0 > lr0) s[ni].x = -1e30f;
                if (c1 > lr0) s[ni].y = -1e30f;
                if (c0 > lr1) s[ni].z = -1e30f;
                if (c1 > lr1) s[ni].w = -1e30f;
            }
        }

        // ---- online softmax ----
        float tm0 = -1e30f, tm1 = -1e30f;
        #pragma unroll
        for (int ni = 0; ni < 8; ni++) {
            tm0 = fmaxf(tm0, fmaxf(s[ni].x, s[ni].y));
            tm1 = fmaxf(tm1, fmaxf(s[ni].z, s[ni].w));
        }
        tm0 = fmaxf(tm0, __shfl_xor_sync(0xffffffffu, tm0, 1));
        tm0 = fmaxf(tm0, __shfl_xor_sync(0xffffffffu, tm0, 2));
        tm1 = fmaxf(tm1, __shfl_xor_sync(0xffffffffu, tm1, 1));
        tm1 = fmaxf(tm1, __shfl_xor_sync(0xffffffffu, tm1, 2));

        const float mn0 = fmaxf(m0r, tm0), mn1 = fmaxf(m1r, tm1);
        const float cr0 = __expf(m0r - mn0), cr1 = __expf(m1r - mn1);
        m0r = mn0; m1r = mn1;

        float ls0 = 0.f, ls1 = 0.f;
        #pragma unroll
        for (int ni = 0; ni < 8; ni++) {
            s[ni].x = __expf(s[ni].x - mn0);
            s[ni].y = __expf(s[ni].y - mn0);
            s[ni].z = __expf(s[ni].z - mn1);
            s[ni].w = __expf(s[ni].w - mn1);
            ls0 += s[ni].x + s[ni].y;
            ls1 += s[ni].z + s[ni].w;
        }
        ls0 += __shfl_xor_sync(0xffffffffu, ls0, 1);
        ls0 += __shfl_xor_sync(0xffffffffu, ls0, 2);
        ls1 += __shfl_xor_sync(0xffffffffu, ls1, 1);
        ls1 += __shfl_xor_sync(0xffffffffu, ls1, 2);
        l0 = l0 * cr0 + ls0;
        l1 = l1 * cr1 + ls1;

        #pragma unroll
        for (int ni = 0; ni < 8; ni++) {
            o[ni].x *= cr0; o[ni].y *= cr0;
            o[ni].z *= cr1; o[ni].w *= cr1;
        }

        // ---- write P into Ks region (own warp rows only) ----
        __syncthreads();   // all warps done reading Ks for S
        #pragma unroll
        for (int ni = 0; ni < 8; ni++) {
            const int c0 = ni * 8 + 2 * tg;
            Ks[lr0][c0]     = __uint_as_float(f2tf32(s[ni].x));
            Ks[lr0][c0 + 1] = __uint_as_float(f2tf32(s[ni].y));
            Ks[lr1][c0]     = __uint_as_float(f2tf32(s[ni].z));
            Ks[lr1][c0 + 1] = __uint_as_float(f2tf32(s[ni].w));
        }
        __syncwarp();

        // ---- O += P * V ----
        #pragma unroll
        for (int ks = 0; ks < 8; ks++) {
            const int kk = ks * 8;
            uint32_t af[4];
            af[0] = __float_as_uint(Ks[lr0][kk + tg]);
            af[1] = __float_as_uint(Ks[lr1][kk + tg]);
            af[2] = __float_as_uint(Ks[lr0][kk + tg + 4]);
            af[3] = __float_as_uint(Ks[lr1][kk + tg + 4]);
            #pragma unroll
            for (int ni = 0; ni < 8; ni++) {
                uint32_t bfr[2];
                bfr[0] = __float_as_uint(Vs[kk + tg][ni * 8 + g]);
                bfr[1] = __float_as_uint(Vs[kk + tg + 4][ni * 8 + g]);
                mma_tf32(o[ni], af, bfr);
            }
        }
    }

    // ---- epilogue: normalize and write to g_A ----
    const float inv0 = 1.f / l0, inv1 = 1.f / l1;
    const int b = bh >> 4, h = bh & 15;
    const int t0 = q0 + lr0, t1 = q0 + lr1;
    float* d0p = g_A + ((size_t)(b * SEQ + t0)) * CMODEL + h * HDIM;
    float* d1p = g_A + ((size_t)(b * SEQ + t1)) * CMODEL + h * HDIM;
    #pragma unroll
    for (int ni = 0; ni < 8; ni++) {
        const int c0 = ni * 8 + 2 * tg;
        d0p[c0]     = o[ni].x * inv0;
        d0p[c0 + 1] = o[ni].y * inv0;
        d1p[c0]     = o[ni].z * inv1;
        d1p[c0 + 1] = o[ni].w * inv1;
    }
}

// ---------------------------------------------------------------------------
// Kernel 3: output projection + bias -> d_out
// ---------------------------------------------------------------------------
__global__ __launch_bounds__(256) void proj_gemm_kernel(
    const float* __restrict__ wo, const float* __restrict__ bias,
    float* __restrict__ out)
{
    GEMM_MAINLOOP(g_A, wo)

    #pragma unroll
    for (int mi = 0; mi < 4; mi++) {
        #pragma unroll
        for (int ni = 0; ni < 4; ni++) {
            float4 c = acc[mi][ni];
            const int col = n0 + wn + ni * 8 + 2 * tg;
            const float b0 = bias[col], b1 = bias[col + 1];
            const int r0 = m0 + wm + mi * 16 + g;
            out[(size_t)r0 * CMODEL + col]           = c.x + b0;
            out[(size_t)r0 * CMODEL + col + 1]       = c.y + b1;
            out[(size_t)(r0 + 8) * CMODEL + col]     = c.z + b0;
            out[(size_t)(r0 + 8) * CMODEL + col + 1] = c.w + b1;
        }
    }
}

// ---------------------------------------------------------------------------
extern "C" void kernel_launch(void* const* d_in, const int* in_sizes, int n_in,
                              void* d_out, int out_size)
{
    const float* x      = (const float*)d_in[0];
    const float* qkv_w  = (const float*)d_in[1];
    const float* qkv_b  = (const float*)d_in[2];
    const float* out_w  = (const float*)d_in[3];
    const float* out_b  = (const float*)d_in[4];
    float* out = (float*)d_out;

    qkv_gemm_kernel<<<dim3(3*CMODEL/128, MROWS/128), 256>>>(x, qkv_w, qkv_b);
    attn_kernel<<<dim3(SEQ/64, BH), 128>>>();
    proj_gemm_kernel<<<dim3(CMODEL/128, MROWS/128), 256>>>(out_w, out_b, out);
}

// round 6
// speedup vs baseline: 5.6676x; 2.3541x over previous
#include <cuda_runtime.h>
#include <math.h>
#include <stdint.h>

// Problem constants
#define BATCH 4
#define SEQ   2048
#define CMODEL 1024
#define NHEAD 16
#define HDIM  64
#define BH    (BATCH*NHEAD)          // 64
#define MROWS (BATCH*SEQ)            // 8192

// Scratch (allocation-free rule: __device__ globals)
__device__ float g_Q[(size_t)BH*SEQ*HDIM];   // tf32-rounded, pre-scaled by 1/8
__device__ float g_K[(size_t)BH*SEQ*HDIM];   // tf32-rounded
__device__ float g_V[(size_t)BH*SEQ*HDIM];   // tf32-rounded
__device__ float g_A[(size_t)MROWS*CMODEL];  // attention out, fp32

// log2(10000)/64
#define ROPE_L2 0.20762050593060493f

#define KPAD 20   // GEMM k-stride in shared

__device__ __forceinline__ uint32_t f2tf32(float f) {
    uint32_t r;
    asm("cvt.rna.tf32.f32 %0, %1;" : "=r"(r) : "f"(f));
    return r;
}
__device__ __forceinline__ float tf32f(float f) { return __uint_as_float(f2tf32(f)); }

__device__ __forceinline__ void cp16(float* s, const float* g) {
    uint32_t sa = (uint32_t)__cvta_generic_to_shared(s);
    asm volatile("cp.async.cg.shared.global [%0], [%1], 16;\n" :: "r"(sa), "l"(g));
}
#define CP_COMMIT asm volatile("cp.async.commit_group;\n" ::: "memory")
#define CP_WAIT0  asm volatile("cp.async.wait_group 0;\n" ::: "memory")
#define CP_WAIT1  asm volatile("cp.async.wait_group 1;\n" ::: "memory")

__device__ __forceinline__ void mma_tf32(float4& d, const uint32_t* a, const uint32_t* b) {
    asm volatile(
        "mma.sync.aligned.m16n8k8.row.col.f32.tf32.tf32.f32 "
        "{%0,%1,%2,%3}, {%4,%5,%6,%7}, {%8,%9}, {%0,%1,%2,%3};\n"
        : "+f"(d.x), "+f"(d.y), "+f"(d.z), "+f"(d.w)
        : "r"(a[0]), "r"(a[1]), "r"(a[2]), "r"(a[3]), "r"(b[0]), "r"(b[1]));
}

// Shared mainloop: C[128x128] tile of A(row-major [M][1024]) * B(row-major [N][1024])^T
// cp.async 2-stage double buffer; tf32 cvt applied at fragment load.
#define GEMM_MAINLOOP(APTR, BPTR)                                                   \
    __shared__ float As[2][128][KPAD];                                              \
    __shared__ float Bs[2][128][KPAD];                                              \
    const int tid = threadIdx.x;                                                    \
    const int w = tid >> 5, lane = tid & 31, g = lane >> 2, tg = lane & 3;          \
    const int wm = (w & 1) * 64, wn = (w >> 1) * 32;                                \
    const int m0 = blockIdx.y * 128, n0 = blockIdx.x * 128;                         \
    const int lr = tid >> 1, lc = (tid & 1) * 8;                                    \
    const float* ga = (APTR) + (size_t)(m0 + lr) * CMODEL + lc;                     \
    const float* gb = (BPTR) + (size_t)(n0 + lr) * CMODEL + lc;                     \
    float4 acc[4][4];                                                               \
    _Pragma("unroll")                                                               \
    for (int i = 0; i < 4; i++)                                                     \
        _Pragma("unroll")                                                           \
        for (int j = 0; j < 4; j++) acc[i][j] = make_float4(0.f, 0.f, 0.f, 0.f);    \
    cp16(&As[0][lr][lc], ga); cp16(&As[0][lr][lc + 4], ga + 4);                     \
    cp16(&Bs[0][lr][lc], gb); cp16(&Bs[0][lr][lc + 4], gb + 4);                     \
    CP_COMMIT;                                                                      \
    for (int kt = 0; kt < CMODEL / 16; kt++) {                                      \
        if (kt < CMODEL / 16 - 1) {                                                 \
            const float* pa = ga + (kt + 1) * 16;                                   \
            const float* pb = gb + (kt + 1) * 16;                                   \
            float* sa = &As[(kt + 1) & 1][lr][lc];                                  \
            float* sb = &Bs[(kt + 1) & 1][lr][lc];                                  \
            cp16(sa, pa); cp16(sa + 4, pa + 4);                                     \
            cp16(sb, pb); cp16(sb + 4, pb + 4);                                     \
            CP_COMMIT; CP_WAIT1;                                                    \
        } else { CP_WAIT0; }                                                        \
        __syncthreads();                                                            \
        const int buf = kt & 1;                                                     \
        _Pragma("unroll")                                                           \
        for (int ks = 0; ks < 2; ks++) {                                            \
            const int kk = ks * 8;                                                  \
            uint32_t af[4][4], bf[4][2];                                            \
            _Pragma("unroll")                                                       \
            for (int mi = 0; mi < 4; mi++) {                                        \
                const int rbase = wm + mi * 16;                                     \
                af[mi][0] = f2tf32(As[buf][rbase + g][kk + tg]);                    \
                af[mi][1] = f2tf32(As[buf][rbase + g + 8][kk + tg]);                \
                af[mi][2] = f2tf32(As[buf][rbase + g][kk + tg + 4]);                \
                af[mi][3] = f2tf32(As[buf][rbase + g + 8][kk + tg + 4]);            \
            }                                                                       \
            _Pragma("unroll")                                                       \
            for (int ni = 0; ni < 4; ni++) {                                        \
                const int cbase = wn + ni * 8;                                      \
                bf[ni][0] = f2tf32(Bs[buf][cbase + g][kk + tg]);                    \
                bf[ni][1] = f2tf32(Bs[buf][cbase + g][kk + tg + 4]);                \
            }                                                                       \
            _Pragma("unroll")                                                       \
            for (int mi = 0; mi < 4; mi++)                                          \
                _Pragma("unroll")                                                   \
                for (int ni = 0; ni < 4; ni++)                                      \
                    mma_tf32(acc[mi][ni], af[mi], bf[ni]);                          \
        }                                                                           \
        __syncthreads();                                                            \
    }

// ---------------------------------------------------------------------------
// Kernel 1: QKV GEMM + bias + RoPE -> g_Q (scaled, tf32), g_K (tf32), g_V (tf32)
// ---------------------------------------------------------------------------
__global__ __launch_bounds__(256) void qkv_gemm_kernel(
    const float* __restrict__ x, const float* __restrict__ wq,
    const float* __restrict__ bias)
{
    GEMM_MAINLOOP(x, wq)

    #pragma unroll
    for (int mi = 0; mi < 4; mi++) {
        #pragma unroll
        for (int ni = 0; ni < 4; ni++) {
            float4 c = acc[mi][ni];
            const int col = n0 + wn + ni * 8 + 2 * tg;   // even
            const int which = col >> 10;                 // 0=q,1=k,2=v
            const int cc = col & 1023;
            const int h = cc >> 6;
            const int d0 = cc & 63;
            const float b0 = bias[col], b1 = bias[col + 1];
            const float invf = exp2f(-(float)d0 * ROPE_L2);
            const int r0 = m0 + wm + mi * 16 + g;
            #pragma unroll
            for (int half = 0; half < 2; half++) {
                const int r = r0 + half * 8;
                float v0 = (half ? c.z : c.x) + b0;
                float v1 = (half ? c.w : c.y) + b1;
                const int b = r >> 11;
                const int t = r & (SEQ - 1);
                const size_t base = ((size_t)(b * NHEAD + h) * SEQ + t) * HDIM + d0;
                if (which == 2) {
                    g_V[base]     = tf32f(v0);
                    g_V[base + 1] = tf32f(v1);
                } else {
                    float s, co;
                    sincosf((float)t * invf, &s, &co);
                    float r0v = v0 * co - v1 * s;
                    float r1v = v0 * s  + v1 * co;
                    if (which == 0) {  // pre-scale Q by 1/sqrt(64)
                        g_Q[base]     = tf32f(r0v * 0.125f);
                        g_Q[base + 1] = tf32f(r1v * 0.125f);
                    } else {
                        g_K[base]     = tf32f(r0v);
                        g_K[base + 1] = tf32f(r1v);
                    }
                }
            }
        }
    }
}

// ---------------------------------------------------------------------------
// Kernel 2: causal flash attention, tf32 mma.
// 128 threads (4 warps); Br=64 (16 rows/warp), Bc=32, double-buffered cp.async
// K/V staging; P kept in registers (shuffle permute into A-fragment layout).
// ---------------------------------------------------------------------------
__global__ __launch_bounds__(128, 4) void attn_kernel()
{
    __shared__ float Ks[2][32][68];   // [buf][key][dim]
    __shared__ float Vs[2][32][72];   // [buf][key][dim]

    const int tid = threadIdx.x;
    const int w = tid >> 5, lane = tid & 31, g = lane >> 2, tg = lane & 3;
    const int wq0 = w * 16;
    const int bh = blockIdx.y;
    const int q0 = ((int)gridDim.x - 1 - (int)blockIdx.x) * 64;  // heavy blocks first
    const size_t bhbase = (size_t)bh * SEQ * HDIM;
    const int lr0 = wq0 + g, lr1 = wq0 + g + 8;

#define ATTN_STAGE(B, S0)                                                        \
    {                                                                            \
        _Pragma("unroll")                                                        \
        for (int i = 0; i < 4; i++) {                                            \
            const int idx = tid + i * 128;                                       \
            const int r = idx >> 4, c = (idx & 15) * 4;                          \
            cp16(&Ks[B][r][c], g_K + bhbase + (size_t)((S0) + r) * HDIM + c);    \
            cp16(&Vs[B][r][c], g_V + bhbase + (size_t)((S0) + r) * HDIM + c);    \
        }                                                                        \
        CP_COMMIT;                                                               \
    }

    const int ntiles = q0 / 32 + 2;
    ATTN_STAGE(0, 0)
    ATTN_STAGE(1, 32)

    // Q fragments straight from gmem (already tf32, already scaled)
    uint32_t qf[8][4];
    {
        const float* qb = g_Q + bhbase + (size_t)q0 * HDIM;
        #pragma unroll
        for (int ks = 0; ks < 8; ks++) {
            const int kk = ks * 8;
            qf[ks][0] = __float_as_uint(qb[(size_t)lr0 * HDIM + kk + tg]);
            qf[ks][1] = __float_as_uint(qb[(size_t)lr1 * HDIM + kk + tg]);
            qf[ks][2] = __float_as_uint(qb[(size_t)lr0 * HDIM + kk + tg + 4]);
            qf[ks][3] = __float_as_uint(qb[(size_t)lr1 * HDIM + kk + tg + 4]);
        }
    }

    float4 o[8];
    #pragma unroll
    for (int ni = 0; ni < 8; ni++) o[ni] = make_float4(0.f, 0.f, 0.f, 0.f);
    float m0r = -1e30f, m1r = -1e30f, l0 = 0.f, l1 = 0.f;

    for (int it = 0; it < ntiles; it++) {
        const int s0 = it * 32;
        if (it + 1 < ntiles) { CP_WAIT1; } else { CP_WAIT0; }
        __syncthreads();
        const int b = it & 1;

        // ---- S = Q * K^T (64 warp rows x 32 keys) ----
        float4 s[4];
        #pragma unroll
        for (int ni = 0; ni < 4; ni++) s[ni] = make_float4(0.f, 0.f, 0.f, 0.f);
        #pragma unroll
        for (int ks = 0; ks < 8; ks++) {
            const int kk = ks * 8;
            #pragma unroll
            for (int ni = 0; ni < 4; ni++) {
                uint32_t bfr[2];
                bfr[0] = __float_as_uint(Ks[b][ni * 8 + g][kk + tg]);
                bfr[1] = __float_as_uint(Ks[b][ni * 8 + g][kk + tg + 4]);
                mma_tf32(s[ni], qf[ks], bfr);
            }
        }

        // ---- causal mask (only tiles that can cross the diagonal) ----
        if (s0 + 31 > q0) {
            #pragma unroll
            for (int ni = 0; ni < 4; ni++) {
                const int c0 = s0 + ni * 8 + 2 * tg, c1 = c0 + 1;
                const int t0 = q0 + lr0, t1 = q0 + lr1;
                if (c0 > t0) s[ni].x = -1e30f;
                if (c1 > t0) s[ni].y = -1e30f;
                if (c0 > t1) s[ni].z = -1e30f;
                if (c1 > t1) s[ni].w = -1e30f;
            }
        }

        // ---- online softmax ----
        float tm0 = -1e30f, tm1 = -1e30f;
        #pragma unroll
        for (int ni = 0; ni < 4; ni++) {
            tm0 = fmaxf(tm0, fmaxf(s[ni].x, s[ni].y));
            tm1 = fmaxf(tm1, fmaxf(s[ni].z, s[ni].w));
        }
        tm0 = fmaxf(tm0, __shfl_xor_sync(0xffffffffu, tm0, 1));
        tm0 = fmaxf(tm0, __shfl_xor_sync(0xffffffffu, tm0, 2));
        tm1 = fmaxf(tm1, __shfl_xor_sync(0xffffffffu, tm1, 1));
        tm1 = fmaxf(tm1, __shfl_xor_sync(0xffffffffu, tm1, 2));

        const float mn0 = fmaxf(m0r, tm0), mn1 = fmaxf(m1r, tm1);
        const float cr0 = __expf(m0r - mn0), cr1 = __expf(m1r - mn1);
        m0r = mn0; m1r = mn1;

        float ls0 = 0.f, ls1 = 0.f;
        #pragma unroll
        for (int ni = 0; ni < 4; ni++) {
            s[ni].x = __expf(s[ni].x - mn0);
            s[ni].y = __expf(s[ni].y - mn0);
            s[ni].z = __expf(s[ni].z - mn1);
            s[ni].w = __expf(s[ni].w - mn1);
            ls0 += s[ni].x + s[ni].y;
            ls1 += s[ni].z + s[ni].w;
        }
        ls0 += __shfl_xor_sync(0xffffffffu, ls0, 1);
        ls0 += __shfl_xor_sync(0xffffffffu, ls0, 2);
        ls1 += __shfl_xor_sync(0xffffffffu, ls1, 1);
        ls1 += __shfl_xor_sync(0xffffffffu, ls1, 2);
        l0 = l0 * cr0 + ls0;
        l1 = l1 * cr1 + ls1;

        #pragma unroll
        for (int ni = 0; ni < 8; ni++) {
            o[ni].x *= cr0; o[ni].y *= cr0;
            o[ni].z *= cr1; o[ni].w *= cr1;
        }

        // ---- P (registers) -> A-fragment layout via shuffles; O += P * V ----
        uint32_t px[4], py[4], pz[4], pw[4];
        #pragma unroll
        for (int ni = 0; ni < 4; ni++) {
            px[ni] = f2tf32(s[ni].x); py[ni] = f2tf32(s[ni].y);
            pz[ni] = f2tf32(s[ni].z); pw[ni] = f2tf32(s[ni].w);
        }
        const int src0 = (lane & ~3) | (tg >> 1);
        const int src1 = src0 + 2;
        #pragma unroll
        for (int ks2 = 0; ks2 < 4; ks2++) {
            const uint32_t x0 = __shfl_sync(0xffffffffu, px[ks2], src0);
            const uint32_t y0 = __shfl_sync(0xffffffffu, py[ks2], src0);
            const uint32_t z0 = __shfl_sync(0xffffffffu, pz[ks2], src0);
            const uint32_t w0 = __shfl_sync(0xffffffffu, pw[ks2], src0);
            const uint32_t x1 = __shfl_sync(0xffffffffu, px[ks2], src1);
            const uint32_t y1 = __shfl_sync(0xffffffffu, py[ks2], src1);
            const uint32_t z1 = __shfl_sync(0xffffffffu, pz[ks2], src1);
            const uint32_t w1 = __shfl_sync(0xffffffffu, pw[ks2], src1);
            uint32_t af[4];
            af[0] = (tg & 1) ? y0 : x0;
            af[1] = (tg & 1) ? w0 : z0;
            af[2] = (tg & 1) ? y1 : x1;
            af[3] = (tg & 1) ? w1 : z1;
            const int kk = ks2 * 8;
            #pragma unroll
            for (int ni = 0; ni < 8; ni++) {
                uint32_t bfr[2];
                bfr[0] = __float_as_uint(Vs[b][kk + tg][ni * 8 + g]);
                bfr[1] = __float_as_uint(Vs[b][kk + tg + 4][ni * 8 + g]);
                mma_tf32(o[ni], af, bfr);
            }
        }

        __syncthreads();
        if (it + 2 < ntiles) ATTN_STAGE(it & 1, s0 + 64)
    }

    // ---- epilogue: normalize and write to g_A ----
    const float inv0 = 1.f / l0, inv1 = 1.f / l1;
    const int b2 = bh >> 4, h = bh & 15;
    const int t0 = q0 + lr0, t1 = q0 + lr1;
    float* d0p = g_A + ((size_t)(b2 * SEQ + t0)) * CMODEL + h * HDIM;
    float* d1p = g_A + ((size_t)(b2 * SEQ + t1)) * CMODEL + h * HDIM;
    #pragma unroll
    for (int ni = 0; ni < 8; ni++) {
        const int c0 = ni * 8 + 2 * tg;
        d0p[c0]     = o[ni].x * inv0;
        d0p[c0 + 1] = o[ni].y * inv0;
        d1p[c0]     = o[ni].z * inv1;
        d1p[c0 + 1] = o[ni].w * inv1;
    }
#undef ATTN_STAGE
}

// ---------------------------------------------------------------------------
// Kernel 3: output projection + bias -> d_out
// ---------------------------------------------------------------------------
__global__ __launch_bounds__(256) void proj_gemm_kernel(
    const float* __restrict__ wo, const float* __restrict__ bias,
    float* __restrict__ out)
{
    GEMM_MAINLOOP(g_A, wo)

    #pragma unroll
    for (int mi = 0; mi < 4; mi++) {
        #pragma unroll
        for (int ni = 0; ni < 4; ni++) {
            float4 c = acc[mi][ni];
            const int col = n0 + wn + ni * 8 + 2 * tg;
            const float b0 = bias[col], b1 = bias[col + 1];
            const int r0 = m0 + wm + mi * 16 + g;
            out[(size_t)r0 * CMODEL + col]           = c.x + b0;
            out[(size_t)r0 * CMODEL + col + 1]       = c.y + b1;
            out[(size_t)(r0 + 8) * CMODEL + col]     = c.z + b0;
            out[(size_t)(r0 + 8) * CMODEL + col + 1] = c.w + b1;
        }
    }
}

// ---------------------------------------------------------------------------
extern "C" void kernel_launch(void* const* d_in, const int* in_sizes, int n_in,
                              void* d_out, int out_size)
{
    const float* x      = (const float*)d_in[0];
    const float* qkv_w  = (const float*)d_in[1];
    const float* qkv_b  = (const float*)d_in[2];
    const float* out_w  = (const float*)d_in[3];
    const float* out_b  = (const float*)d_in[4];
    float* out = (float*)d_out;

    qkv_gemm_kernel<<<dim3(3*CMODEL/128, MROWS/128), 256>>>(x, qkv_w, qkv_b);
    attn_kernel<<<dim3(SEQ/64, BH), 128>>>();
    proj_gemm_kernel<<<dim3(CMODEL/128, MROWS/128), 256>>>(out_w, out_b, out);
}